// round 3
// baseline (speedup 1.0000x reference)
#include <cuda_runtime.h>
#include <cuda_bf16.h>
#include <cstdint>

#define NROW 8192

__device__ float4 g_zn[NROW * 32];
__device__ uint4  g_zbf[NROW * 16];   // normalized bf16 rows, 256B each
__device__ float2 g_meta[NROW];       // (sq_j, bitcast(label | subj<<16))
__device__ unsigned long long g_pos[NROW];
__device__ unsigned long long g_neg[NROW];
__device__ float g_per[NROW];
__device__ int   g_vld[NROW];

static __device__ __forceinline__ unsigned ford(float f) {
    unsigned u = __float_as_uint(f);
    return (u & 0x80000000u) ? ~u : (u | 0x80000000u);
}
static __device__ __forceinline__ uint32_t smem_u32(const void* p) {
    uint32_t a;
    asm("{ .reg .u64 t; cvta.to.shared.u64 t, %1; cvt.u32.u64 %0, t; }" : "=r"(a) : "l"(p));
    return a;
}
static __device__ __forceinline__ void cpa16(uint32_t dst, const void* src) {
    asm volatile("cp.async.cg.shared.global [%0], [%1], 16;" :: "r"(dst), "l"(src));
}
static __device__ __forceinline__ void cpwait() {
    asm volatile("cp.async.commit_group;\n\tcp.async.wait_group 0;" ::: "memory");
}
static __device__ __forceinline__ void ldm4(uint32_t& r0, uint32_t& r1, uint32_t& r2,
                                            uint32_t& r3, uint32_t addr) {
    asm volatile("ldmatrix.sync.aligned.m8n8.x4.shared.b16 {%0,%1,%2,%3}, [%4];"
                 : "=r"(r0), "=r"(r1), "=r"(r2), "=r"(r3) : "r"(addr));
}
static __device__ __forceinline__ void mma16816(float* c, const uint32_t* a,
                                                uint32_t b0, uint32_t b1) {
    asm volatile(
        "mma.sync.aligned.m16n8k16.row.col.f32.bf16.bf16.f32 "
        "{%0,%1,%2,%3}, {%4,%5,%6,%7}, {%8,%9}, {%0,%1,%2,%3};"
        : "+f"(c[0]), "+f"(c[1]), "+f"(c[2]), "+f"(c[3])
        : "r"(a[0]), "r"(a[1]), "r"(a[2]), "r"(a[3]), "r"(b0), "r"(b1));
}
// row-major 256B rows; 16B chunk index XOR-swizzled by row for conflict-free ldmatrix
static __device__ __forceinline__ uint32_t sw_off(int row, int chunk) {
    return (uint32_t)(row * 256 + ((chunk ^ (row & 7)) << 4));
}

__global__ void k_prep(const float* __restrict__ z, const int* __restrict__ lab,
                       const int* __restrict__ sub) {
    int row = blockIdx.x * 8 + (threadIdx.x >> 5);
    int lane = threadIdx.x & 31;
    float4 v = reinterpret_cast<const float4*>(z)[row * 32 + lane];
    float ss = v.x * v.x + v.y * v.y + v.z * v.z + v.w * v.w;
#pragma unroll
    for (int o = 16; o; o >>= 1) ss += __shfl_xor_sync(0xFFFFFFFFu, ss, o);
    float inv = 1.0f / fmaxf(sqrtf(ss), 1e-12f);
    float4 zn = make_float4(v.x * inv, v.y * inv, v.z * inv, v.w * inv);
    g_zn[row * 32 + lane] = zn;
    unsigned s0 = __bfloat16_as_ushort(__float2bfloat16_rn(zn.x));
    unsigned s1 = __bfloat16_as_ushort(__float2bfloat16_rn(zn.y));
    unsigned s2 = __bfloat16_as_ushort(__float2bfloat16_rn(zn.z));
    unsigned s3 = __bfloat16_as_ushort(__float2bfloat16_rn(zn.w));
    uint2 pk;
    pk.x = s0 | (s1 << 16);
    pk.y = s2 | (s3 << 16);
    reinterpret_cast<uint2*>(g_zbf)[row * 32 + lane] = pk;
    float sq = zn.x * zn.x + zn.y * zn.y + zn.z * zn.z + zn.w * zn.w;
#pragma unroll
    for (int o = 16; o; o >>= 1) sq += __shfl_xor_sync(0xFFFFFFFFu, sq, o);
    if (lane == 0) {
        unsigned packed = ((unsigned)lab[row] & 0xFFFFu) | (((unsigned)sub[row] & 0xFFFFu) << 16);
        g_meta[row] = make_float2(sq, __uint_as_float(packed));
        g_pos[row] = 0ull;
        g_neg[row] = 0xFFFFFFFFFFFFFFFFull;
    }
}

struct MineSmem {
    uint4 B[2048];     // 32KB tile (also used to stage A once)
    float2 meta[128];  // 1KB
};

__global__ void __launch_bounds__(256, 1) k_mine() {
    __shared__ MineSmem sm;
    const int tid = threadIdx.x, w = tid >> 5, lane = tid & 31;
    const int ib = blockIdx.x >> 1, js = blockIdx.x & 1;
    const int row0 = ib * 128;
    const uint32_t sbB = smem_u32(sm.B);
    const uint32_t sbM = smem_u32(sm.meta);

    // stage A block (128 rows x 256B) swizzled
    for (int idx = tid; idx < 2048; idx += 256)
        cpa16(sbB + sw_off(idx >> 4, idx & 15),
              &g_zbf[(size_t)(row0 + (idx >> 4)) * 16 + (idx & 15)]);
    cpwait();
    __syncthreads();

    // A fragments: warp w owns rows [w*16, w*16+16)
    uint32_t A[8][4];
    {
        int r = w * 16 + ((lane >> 3) & 1) * 8 + (lane & 7);
        int cb = lane >> 4;
#pragma unroll
        for (int s = 0; s < 8; s++)
            ldm4(A[s][0], A[s][1], A[s][2], A[s][3], sbB + sw_off(r, 2 * s + cb));
    }

    const int r0g = row0 + w * 16 + (lane >> 2);
    const unsigned mypk0 = __float_as_uint(__ldg(&g_meta[r0g].y));
    const unsigned mypk1 = __float_as_uint(__ldg(&g_meta[r0g + 8].y));
    float bpk0 = -1e30f, bnk0 = 1e30f, bpk1 = -1e30f, bnk1 = 1e30f;
    int bpj0 = -1, bnj0 = -1, bpj1 = -1, bnj1 = -1;

    for (int t = 0; t < 32; t++) {
        const int jbase = js * 4096 + t * 128;
        __syncthreads();  // prior ldmatrix/meta reads done before overwrite
        for (int idx = tid; idx < 2048; idx += 256)
            cpa16(sbB + sw_off(idx >> 4, idx & 15),
                  &g_zbf[(size_t)(jbase + (idx >> 4)) * 16 + (idx & 15)]);
        if (tid < 64) cpa16(sbM + tid * 16, &g_meta[jbase + tid * 2]);
        cpwait();
        __syncthreads();

        float acc[16][4];
#pragma unroll
        for (int i = 0; i < 16; i++)
#pragma unroll
            for (int e = 0; e < 4; e++) acc[i][e] = 0.f;

#pragma unroll
        for (int np = 0; np < 8; np++) {
            const int n = np * 16 + ((lane >> 4) << 3) + (lane & 7);
            const int cadd = (lane >> 3) & 1;
#pragma unroll
            for (int s = 0; s < 8; s++) {
                uint32_t b0, b1, b2, b3;
                ldm4(b0, b1, b2, b3, sbB + sw_off(n, 2 * s + cadd));
                mma16816(acc[2 * np], A[s], b0, b1);
                mma16816(acc[2 * np + 1], A[s], b2, b3);
            }
        }

        // epilogue: masked running argmax/argmin on key = sq_j - 2*dot
#pragma unroll
        for (int nt = 0; nt < 16; nt++) {
            const int cb = nt * 8 + (lane & 3) * 2;
            float4 mm = *reinterpret_cast<const float4*>(&sm.meta[cb]);
            const int j0 = jbase + cb;
            // e: 0=(r0,c0) 1=(r0,c0+1) 2=(r1,c0) 3=(r1,c0+1)
#pragma unroll
            for (int e = 0; e < 4; e++) {
                float sq = (e & 1) ? mm.z : mm.x;
                unsigned pk = __float_as_uint((e & 1) ? mm.w : mm.y);
                unsigned my = (e >> 1) ? mypk1 : mypk0;
                float key = fmaf(-2.f, acc[nt][e], sq);
                unsigned diff = pk ^ my;
                bool pos = ((diff & 0xFFFFu) == 0u) & (diff != 0u);
                bool neg = (diff - 1u) < 0xFFFFu;
                int j = j0 + (e & 1);
                if (e >> 1) {
                    if (pos && key > bpk1) { bpk1 = key; bpj1 = j; }
                    if (neg && key < bnk1) { bnk1 = key; bnj1 = j; }
                } else {
                    if (pos && key > bpk0) { bpk0 = key; bpj0 = j; }
                    if (neg && key < bnk0) { bnk0 = key; bnj0 = j; }
                }
            }
        }
    }

    // pack (key, index) with first-index tie-break; quad-reduce; atomic merge
    unsigned long long P0 = (bpj0 < 0) ? 0ull
        : (((unsigned long long)ford(bpk0) << 32) | (unsigned)(0xFFFFFFFFu - (unsigned)bpj0));
    unsigned long long P1 = (bpj1 < 0) ? 0ull
        : (((unsigned long long)ford(bpk1) << 32) | (unsigned)(0xFFFFFFFFu - (unsigned)bpj1));
    unsigned long long N0 = (bnj0 < 0) ? ~0ull
        : (((unsigned long long)ford(bnk0) << 32) | (unsigned)bnj0);
    unsigned long long N1 = (bnj1 < 0) ? ~0ull
        : (((unsigned long long)ford(bnk1) << 32) | (unsigned)bnj1);
#pragma unroll
    for (int o = 1; o <= 2; o <<= 1) {
        unsigned long long q;
        q = __shfl_xor_sync(0xFFFFFFFFu, P0, o); if (q > P0) P0 = q;
        q = __shfl_xor_sync(0xFFFFFFFFu, P1, o); if (q > P1) P1 = q;
        q = __shfl_xor_sync(0xFFFFFFFFu, N0, o); if (q < N0) N0 = q;
        q = __shfl_xor_sync(0xFFFFFFFFu, N1, o); if (q < N1) N1 = q;
    }
    if ((lane & 3) == 0) {
        if (P0) atomicMax(&g_pos[r0g], P0);
        if (P1) atomicMax(&g_pos[r0g + 8], P1);
        if (~N0) atomicMin(&g_neg[r0g], N0);
        if (~N1) atomicMin(&g_neg[r0g + 8], N1);
    }
}

__global__ void k_pair() {
    int i = blockIdx.x * 8 + (threadIdx.x >> 5);
    int lane = threadIdx.x & 31;
    unsigned long long bp = g_pos[i], bn = g_neg[i];
    bool valid = (bp != 0ull) && (bn != 0xFFFFFFFFFFFFFFFFull);
    int pj = (int)(0xFFFFFFFFu - (unsigned)(bp & 0xFFFFFFFFu));
    int nj = (int)(unsigned)(bn & 0xFFFFFFFFull);
    if (!valid) { pj = 0; nj = 0; }
    float4 a = g_zn[i * 32 + lane];
    float4 p = g_zn[pj * 32 + lane];
    float4 n = g_zn[nj * 32 + lane];
    const float e = 1e-6f;
    float dx, s1 = 0.f, s2 = 0.f;
    dx = a.x - p.x + e; s1 += dx * dx;
    dx = a.y - p.y + e; s1 += dx * dx;
    dx = a.z - p.z + e; s1 += dx * dx;
    dx = a.w - p.w + e; s1 += dx * dx;
    dx = a.x - n.x + e; s2 += dx * dx;
    dx = a.y - n.y + e; s2 += dx * dx;
    dx = a.z - n.z + e; s2 += dx * dx;
    dx = a.w - n.w + e; s2 += dx * dx;
#pragma unroll
    for (int o = 16; o; o >>= 1) {
        s1 += __shfl_xor_sync(0xFFFFFFFFu, s1, o);
        s2 += __shfl_xor_sync(0xFFFFFFFFu, s2, o);
    }
    if (lane == 0) {
        float per = fmaxf(sqrtf(s1) - sqrtf(s2) + 0.2f, 0.f);
        g_per[i] = valid ? per : 0.f;
        g_vld[i] = valid ? 1 : 0;
    }
}

__global__ void k_reduce(float* out) {
    __shared__ float ssum[1024];
    __shared__ int scnt[1024];
    int tid = threadIdx.x;
    float s = 0.f;
    int c = 0;
#pragma unroll
    for (int k = 0; k < 8; k++) {
        s += g_per[tid * 8 + k];
        c += g_vld[tid * 8 + k];
    }
    ssum[tid] = s;
    scnt[tid] = c;
    __syncthreads();
    for (int o = 512; o; o >>= 1) {
        if (tid < o) {
            ssum[tid] += ssum[tid + o];
            scnt[tid] += scnt[tid + o];
        }
        __syncthreads();
    }
    if (tid == 0) out[0] = scnt[0] > 0 ? ssum[0] / (float)scnt[0] : 0.f;
}

extern "C" void kernel_launch(void* const* d_in, const int* in_sizes, int n_in,
                              void* d_out, int out_size) {
    const float* z = (const float*)d_in[0];
    const int* lab = (const int*)d_in[1];
    const int* sub = (const int*)d_in[2];
    k_prep<<<1024, 256>>>(z, lab, sub);
    k_mine<<<128, 256>>>();
    k_pair<<<1024, 256>>>();
    k_reduce<<<1, 1024>>>((float*)d_out);
}

// round 6
// speedup vs baseline: 1.2713x; 1.2713x over previous
#include <cuda_runtime.h>
#include <cuda_bf16.h>
#include <cstdint>

#define NROW 8192

__device__ float4 g_zn[NROW * 32];
__device__ uint4  g_zbf[NROW * 16];   // normalized bf16 rows, 256B each
__device__ float2 g_meta[NROW];       // (sq_j, bitcast(dual-code pk))
__device__ unsigned long long g_pos[NROW];
__device__ unsigned long long g_neg[NROW];
__device__ unsigned long long g_acc;
__device__ unsigned g_done;

static __device__ __forceinline__ unsigned ford(float f) {
    unsigned u = __float_as_uint(f);
    return (u & 0x80000000u) ? ~u : (u | 0x80000000u);
}
static __device__ __forceinline__ uint32_t smem_u32(const void* p) {
    uint32_t a;
    asm("{ .reg .u64 t; cvta.to.shared.u64 t, %1; cvt.u32.u64 %0, t; }" : "=r"(a) : "l"(p));
    return a;
}
static __device__ __forceinline__ void cpa16(uint32_t dst, const void* src) {
    asm volatile("cp.async.cg.shared.global [%0], [%1], 16;" :: "r"(dst), "l"(src));
}
static __device__ __forceinline__ void cpcommit() {
    asm volatile("cp.async.commit_group;" ::: "memory");
}
template <int N> static __device__ __forceinline__ void cpwaitn() {
    asm volatile("cp.async.wait_group %0;" :: "n"(N) : "memory");
}
static __device__ __forceinline__ void ldm4(uint32_t& r0, uint32_t& r1, uint32_t& r2,
                                            uint32_t& r3, uint32_t addr) {
    asm volatile("ldmatrix.sync.aligned.m8n8.x4.shared.b16 {%0,%1,%2,%3}, [%4];"
                 : "=r"(r0), "=r"(r1), "=r"(r2), "=r"(r3) : "r"(addr));
}
static __device__ __forceinline__ void mma16816(float* c, const uint32_t* a,
                                                uint32_t b0, uint32_t b1) {
    asm volatile(
        "mma.sync.aligned.m16n8k16.row.col.f32.bf16.bf16.f32 "
        "{%0,%1,%2,%3}, {%4,%5,%6,%7}, {%8,%9}, {%0,%1,%2,%3};"
        : "+f"(c[0]), "+f"(c[1]), "+f"(c[2]), "+f"(c[3])
        : "r"(a[0]), "r"(a[1]), "r"(a[2]), "r"(a[3]), "r"(b0), "r"(b1));
}
static __device__ __forceinline__ uint32_t sw_off(int row, int chunk) {
    return (uint32_t)(row * 256 + ((chunk ^ (row & 7)) << 4));
}
static __device__ __forceinline__ void upd(float key, unsigned pkj, unsigned my, int j,
                                           float& bpk, int& bpj, float& bnk, int& bnj) {
    unsigned diff = pkj ^ my;
    bool pos = ((diff & 0xFFFFu) - 1u) < 31u;   // same class, diff subject
    bool neg = ((diff >> 16) - 1u) < 15u;       // diff class, same subject
    bool up = pos & (key > bpk);
    bpk = up ? key : bpk;
    bpj = up ? j : bpj;
    bool un = neg & (key < bnk);
    bnk = un ? key : bnk;
    bnj = un ? j : bnj;
}

__global__ void k_prep(const float* __restrict__ z, const int* __restrict__ lab,
                       const int* __restrict__ sub) {
    int row = blockIdx.x * 8 + (threadIdx.x >> 5);
    int lane = threadIdx.x & 31;
    float4 v = reinterpret_cast<const float4*>(z)[row * 32 + lane];
    float ss = v.x * v.x + v.y * v.y + v.z * v.z + v.w * v.w;
#pragma unroll
    for (int o = 16; o; o >>= 1) ss += __shfl_xor_sync(0xFFFFFFFFu, ss, o);
    float inv = 1.0f / fmaxf(sqrtf(ss), 1e-12f);
    float4 zn = make_float4(v.x * inv, v.y * inv, v.z * inv, v.w * inv);
    g_zn[row * 32 + lane] = zn;
    unsigned s0 = __bfloat16_as_ushort(__float2bfloat16_rn(zn.x));
    unsigned s1 = __bfloat16_as_ushort(__float2bfloat16_rn(zn.y));
    unsigned s2 = __bfloat16_as_ushort(__float2bfloat16_rn(zn.z));
    unsigned s3 = __bfloat16_as_ushort(__float2bfloat16_rn(zn.w));
    uint2 pkv;
    pkv.x = s0 | (s1 << 16);
    pkv.y = s2 | (s3 << 16);
    reinterpret_cast<uint2*>(g_zbf)[row * 32 + lane] = pkv;
    float sq = zn.x * zn.x + zn.y * zn.y + zn.z * zn.z + zn.w * zn.w;
#pragma unroll
    for (int o = 16; o; o >>= 1) sq += __shfl_xor_sync(0xFFFFFFFFu, sq, o);
    if (lane == 0) {
        unsigned L = (unsigned)lab[row] & 15u, S = (unsigned)sub[row] & 31u;
        unsigned pk = ((L << 5) | S) | (((S << 4) | L) << 16);
        g_meta[row] = make_float2(sq, __uint_as_float(pk));
        g_pos[row] = 0ull;
        g_neg[row] = 0xFFFFFFFFFFFFFFFFull;
        if (row == 0) { g_acc = 0ull; g_done = 0u; }
    }
}

#define SM_B0 0
#define SM_B1 32768
#define SM_M0 65536
#define SM_M1 66560
#define SM_TOT 67584
#define NT 16

__global__ void __launch_bounds__(256, 2) k_mine() {
    extern __shared__ char dynsm[];
    const int tid = threadIdx.x, w = tid >> 5, lane = tid & 31;
    const int ib = blockIdx.x >> 2, js = blockIdx.x & 3;
    const int row0 = ib * 128;
    const int jb0 = js * 2048;
    const uint32_t sb = smem_u32(dynsm);

    // group0: A block -> B1, tile0 -> B0, meta0 -> M0
    for (int idx = tid; idx < 2048; idx += 256) {
        int r = idx >> 4, q = idx & 15;
        cpa16(sb + SM_B1 + sw_off(r, q), &g_zbf[(size_t)(row0 + r) * 16 + q]);
        cpa16(sb + SM_B0 + sw_off(r, q), &g_zbf[(size_t)(jb0 + r) * 16 + q]);
    }
    if (tid < 64) cpa16(sb + SM_M0 + tid * 16, &g_meta[jb0 + tid * 2]);
    cpcommit();
    cpwaitn<0>();
    __syncthreads();

    uint32_t A[8][4];
    {
        int r = w * 16 + ((lane >> 3) & 1) * 8 + (lane & 7);
        int cb = lane >> 4;
#pragma unroll
        for (int s = 0; s < 8; s++)
            ldm4(A[s][0], A[s][1], A[s][2], A[s][3], sb + SM_B1 + sw_off(r, 2 * s + cb));
    }
    __syncthreads();  // A reads done; B1 reusable

    const int r0g = row0 + w * 16 + (lane >> 2);
    const unsigned my0 = __float_as_uint(__ldg(&g_meta[r0g].y));
    const unsigned my1 = __float_as_uint(__ldg(&g_meta[r0g + 8].y));
    const int q = lane & 3;
    float bpk0[4], bnk0[4], bpk1[4], bnk1[4];
    int bpj0[4], bnj0[4], bpj1[4], bnj1[4];
#pragma unroll
    for (int s = 0; s < 4; s++) {
        bpk0[s] = bpk1[s] = -1e30f;
        bnk0[s] = bnk1[s] = 1e30f;
        bpj0[s] = bnj0[s] = bpj1[s] = bnj1[s] = -1;
    }

    for (int t = 0; t < NT; t++) {
        const int st = t & 1;
        if (t + 1 < NT) {
            const int jb1 = jb0 + (t + 1) * 128;
            const uint32_t bofs = sb + (((t + 1) & 1) ? SM_B1 : SM_B0);
            for (int idx = tid; idx < 2048; idx += 256) {
                int r = idx >> 4, qq = idx & 15;
                cpa16(bofs + sw_off(r, qq), &g_zbf[(size_t)(jb1 + r) * 16 + qq]);
            }
            if (tid < 64)
                cpa16(sb + (((t + 1) & 1) ? SM_M1 : SM_M0) + tid * 16, &g_meta[jb1 + tid * 2]);
            cpcommit();
            cpwaitn<1>();
        } else {
            cpwaitn<0>();
        }
        __syncthreads();

        const uint32_t bB = sb + (st ? SM_B1 : SM_B0);
        const float4* mt = reinterpret_cast<const float4*>(dynsm + (st ? SM_M1 : SM_M0));
        const int jb = jb0 + t * 128;
        const int cadd = (lane >> 3) & 1;
        const int nbase = ((lane >> 4) << 3) + (lane & 7);

#pragma unroll
        for (int np = 0; np < 8; np++) {
            const int n = np * 16 + nbase;
            float a0[4] = {0.f, 0.f, 0.f, 0.f}, a1[4] = {0.f, 0.f, 0.f, 0.f};
#pragma unroll
            for (int s = 0; s < 8; s++) {
                uint32_t b0, b1, b2, b3;
                ldm4(b0, b1, b2, b3, bB + sw_off(n, 2 * s + cadd));
                mma16816(a0, A[s], b0, b1);
                mma16816(a1, A[s], b2, b3);
            }
#pragma unroll
            for (int h = 0; h < 2; h++) {
                const int nt = 2 * np + h;
                const float* av = h ? a1 : a0;
                float4 mm = mt[nt * 4 + q];
                unsigned pk0 = __float_as_uint(mm.y), pk1 = __float_as_uint(mm.w);
                const int j0 = jb + nt * 8 + q * 2;
                const int s = nt & 3;
                upd(fmaf(-2.f, av[0], mm.x), pk0, my0, j0, bpk0[s], bpj0[s], bnk0[s], bnj0[s]);
                upd(fmaf(-2.f, av[1], mm.z), pk1, my0, j0 + 1, bpk0[s], bpj0[s], bnk0[s], bnj0[s]);
                upd(fmaf(-2.f, av[2], mm.x), pk0, my1, j0, bpk1[s], bpj1[s], bnk1[s], bnj1[s]);
                upd(fmaf(-2.f, av[3], mm.z), pk1, my1, j0 + 1, bpk1[s], bpj1[s], bnk1[s], bnj1[s]);
            }
        }
        __syncthreads();
    }

    unsigned long long P0 = 0ull, P1 = 0ull, N0 = ~0ull, N1 = ~0ull;
#pragma unroll
    for (int s = 0; s < 4; s++) {
        if (bpj0[s] >= 0) {
            unsigned long long cd = ((unsigned long long)ford(bpk0[s]) << 32) |
                                    (unsigned)(0xFFFFFFFFu - (unsigned)bpj0[s]);
            if (cd > P0) P0 = cd;
        }
        if (bpj1[s] >= 0) {
            unsigned long long cd = ((unsigned long long)ford(bpk1[s]) << 32) |
                                    (unsigned)(0xFFFFFFFFu - (unsigned)bpj1[s]);
            if (cd > P1) P1 = cd;
        }
        if (bnj0[s] >= 0) {
            unsigned long long cd = ((unsigned long long)ford(bnk0[s]) << 32) | (unsigned)bnj0[s];
            if (cd < N0) N0 = cd;
        }
        if (bnj1[s] >= 0) {
            unsigned long long cd = ((unsigned long long)ford(bnk1[s]) << 32) | (unsigned)bnj1[s];
            if (cd < N1) N1 = cd;
        }
    }
#pragma unroll
    for (int o = 1; o <= 2; o <<= 1) {
        unsigned long long x;
        x = __shfl_xor_sync(0xFFFFFFFFu, P0, o); if (x > P0) P0 = x;
        x = __shfl_xor_sync(0xFFFFFFFFu, P1, o); if (x > P1) P1 = x;
        x = __shfl_xor_sync(0xFFFFFFFFu, N0, o); if (x < N0) N0 = x;
        x = __shfl_xor_sync(0xFFFFFFFFu, N1, o); if (x < N1) N1 = x;
    }
    if ((lane & 3) == 0) {
        if (P0) atomicMax(&g_pos[r0g], P0);
        if (P1) atomicMax(&g_pos[r0g + 8], P1);
        if (~N0) atomicMin(&g_neg[r0g], N0);
        if (~N1) atomicMin(&g_neg[r0g + 8], N1);
    }
}

__global__ void k_pair(float* __restrict__ out) {
    __shared__ float sper[8];
    __shared__ int scnt[8];
    int w = threadIdx.x >> 5, lane = threadIdx.x & 31;
    int i = blockIdx.x * 8 + w;
    unsigned long long bp = g_pos[i], bn = g_neg[i];
    bool valid = (bp != 0ull) && (bn != 0xFFFFFFFFFFFFFFFFull);
    int pj = (int)(0xFFFFFFFFu - (unsigned)(bp & 0xFFFFFFFFull));
    int nj = (int)(unsigned)(bn & 0xFFFFFFFFull);
    if (!valid) { pj = 0; nj = 0; }
    float4 a = g_zn[i * 32 + lane];
    float4 p = g_zn[pj * 32 + lane];
    float4 n = g_zn[nj * 32 + lane];
    const float e = 1e-6f;
    float dx, s1 = 0.f, s2 = 0.f;
    dx = a.x - p.x + e; s1 += dx * dx;
    dx = a.y - p.y + e; s1 += dx * dx;
    dx = a.z - p.z + e; s1 += dx * dx;
    dx = a.w - p.w + e; s1 += dx * dx;
    dx = a.x - n.x + e; s2 += dx * dx;
    dx = a.y - n.y + e; s2 += dx * dx;
    dx = a.z - n.z + e; s2 += dx * dx;
    dx = a.w - n.w + e; s2 += dx * dx;
#pragma unroll
    for (int o = 16; o; o >>= 1) {
        s1 += __shfl_xor_sync(0xFFFFFFFFu, s1, o);
        s2 += __shfl_xor_sync(0xFFFFFFFFu, s2, o);
    }
    if (lane == 0) {
        float per = fmaxf(sqrtf(s1) - sqrtf(s2) + 0.2f, 0.f);
        sper[w] = valid ? per : 0.f;
        scnt[w] = valid ? 1 : 0;
    }
    __syncthreads();
    if (threadIdx.x == 0) {
        float bs = 0.f;
        int bc = 0;
#pragma unroll
        for (int k = 0; k < 8; k++) { bs += sper[k]; bc += scnt[k]; }
        unsigned long long fx = (unsigned long long)(bs * 16777216.0f + 0.5f);
        atomicAdd(&g_acc, (fx << 14) | (unsigned long long)bc);
        __threadfence();
        unsigned old = atomicAdd(&g_done, 1u);
        if (old == gridDim.x - 1) {
            unsigned long long acc = atomicAdd(&g_acc, 0ull);
            unsigned cnt = (unsigned)(acc & 0x3FFFull);
            float sum = (float)(acc >> 14) * (1.0f / 16777216.0f);
            out[0] = cnt ? sum / (float)cnt : 0.f;
        }
    }
}

extern "C" void kernel_launch(void* const* d_in, const int* in_sizes, int n_in,
                              void* d_out, int out_size) {
    const float* z = (const float*)d_in[0];
    const int* lab = (const int*)d_in[1];
    const int* sub = (const int*)d_in[2];
    cudaFuncSetAttribute(k_mine, cudaFuncAttributeMaxDynamicSharedMemorySize, SM_TOT);
    k_prep<<<1024, 256>>>(z, lab, sub);
    k_mine<<<256, 256, SM_TOT>>>();
    k_pair<<<1024, 256>>>((float*)d_out);
}